// round 1
// baseline (speedup 1.0000x reference)
#include <cuda_runtime.h>
#include <cstdint>

// Fixed problem shapes (setup_inputs is deterministic: B=4, S=1024, E=1024, width=768)
#define Bq   4
#define Sq   1024
#define Eq   1024
#define Wd   768
#define Hh   12
#define Dd   64
#define BSq  (Bq*Sq)            // 4096
#define OUT_ELEMS   ((long long)BSq*Wd)                 // 3,145,728
#define ATTN_ELEMS  ((long long)Bq*Hh*Sq*Sq)            // 50,331,648

// Scratch (device globals; no runtime allocation allowed)
__device__ float g_q[BSq*Wd];
__device__ float g_k[BSq*Wd];
__device__ float g_v[BSq*Wd];
__device__ float g_ctx[BSq*Wd];
__device__ float g_attn_fallback[Bq*Hh*Sq*Sq];   // used only if d_out lacks the attn region

#define BM 64
#define BN 64
#define BK 16
#define SPAD 68   // padded row length (floats); keeps float4 alignment, reduces bank conflicts

// Generic 64x64 tile GEMM body.
// A: [64 rows x K], row stride lda, K-contiguous.
// TRANS_B_IS_KN == false: B is [64 n-rows x K], K-contiguous (NT gemm, C = A * B^T)
// TRANS_B_IS_KN == true : B is [K x 64], N-contiguous   (NN gemm, C = A * B)
template <bool B_IS_KN>
__device__ __forceinline__ void gemm_tile_body(const float* __restrict__ A, int lda,
                                               const float* __restrict__ B, int ldb,
                                               int K, float acc[4][4]) {
    __shared__ float As[BK][SPAD];
    __shared__ float Bs[BK][SPAD];
    const int tid = threadIdx.y * 16 + threadIdx.x;

    for (int k0 = 0; k0 < K; k0 += BK) {
        // Load A tile: 64 rows x 16 k
        #pragma unroll
        for (int t = 0; t < 4; t++) {
            int idx = tid + t * 256;
            int kk = idx & 15, m = idx >> 4;
            As[kk][m] = A[(size_t)m * lda + k0 + kk];
        }
        if (!B_IS_KN) {
            #pragma unroll
            for (int t = 0; t < 4; t++) {
                int idx = tid + t * 256;
                int kk = idx & 15, n = idx >> 4;
                Bs[kk][n] = B[(size_t)n * ldb + k0 + kk];
            }
        } else {
            #pragma unroll
            for (int t = 0; t < 4; t++) {
                int idx = tid + t * 256;
                int n = idx & 63, kk = idx >> 6;
                Bs[kk][n] = B[(size_t)(k0 + kk) * ldb + n];
            }
        }
        __syncthreads();

        #pragma unroll
        for (int kk = 0; kk < BK; kk++) {
            float4 a4 = *(const float4*)&As[kk][threadIdx.y * 4];
            float4 b4 = *(const float4*)&Bs[kk][threadIdx.x * 4];
            float av[4] = {a4.x, a4.y, a4.z, a4.w};
            float bv[4] = {b4.x, b4.y, b4.z, b4.w};
            #pragma unroll
            for (int i = 0; i < 4; i++)
                #pragma unroll
                for (int j = 0; j < 4; j++)
                    acc[i][j] += av[i] * bv[j];
        }
        __syncthreads();
    }
}

// ---------------------------------------------------------------------------
// Kernel 1: fused QKV projections. grid(12, 64, 3), block(16,16)
//   out[n, o] = sum_i x[n,i] * W[o,i] + b[o]     (i,o < 768; x row stride 1024)
// ---------------------------------------------------------------------------
__global__ __launch_bounds__(256)
void qkv_kernel(const float* __restrict__ x,
                const float* __restrict__ qw, const float* __restrict__ qb,
                const float* __restrict__ kw, const float* __restrict__ kb,
                const float* __restrict__ vw, const float* __restrict__ vb) {
    const float* W; const float* bias; float* out;
    if (blockIdx.z == 0)      { W = qw; bias = qb; out = g_q; }
    else if (blockIdx.z == 1) { W = kw; bias = kb; out = g_k; }
    else                      { W = vw; bias = vb; out = g_v; }

    const int i0 = blockIdx.y * BM;
    const int n0 = blockIdx.x * BN;
    float acc[4][4] = {};
    gemm_tile_body<false>(x + (size_t)i0 * Eq, Eq, W + (size_t)n0 * Eq, Eq, Wd, acc);

    const int row = i0 + threadIdx.y * 4;
    const int col = n0 + threadIdx.x * 4;
    #pragma unroll
    for (int i = 0; i < 4; i++)
        #pragma unroll
        for (int j = 0; j < 4; j++)
            out[(size_t)(row + i) * Wd + col + j] = acc[i][j] + bias[col + j];
}

// ---------------------------------------------------------------------------
// Kernel 2: masked scores = Q K^T / 8. grid(16, 16, 48), block(16,16)
// ---------------------------------------------------------------------------
__global__ __launch_bounds__(256)
void score_kernel(const int* __restrict__ mask, float* __restrict__ attn_out) {
    float* attnW = attn_out ? attn_out : g_attn_fallback;
    const int z = blockIdx.z;            // b*12 + h
    const int b = z / Hh;
    const int h = z - b * Hh;
    const float* Qp = g_q + (size_t)b * Sq * Wd + h * Dd;
    const float* Kp = g_k + (size_t)b * Sq * Wd + h * Dd;

    const int i0 = blockIdx.y * BM;
    const int j0 = blockIdx.x * BN;
    float acc[4][4] = {};
    gemm_tile_body<false>(Qp + (size_t)i0 * Wd, Wd, Kp + (size_t)j0 * Wd, Wd, Dd, acc);

    const int row = i0 + threadIdx.y * 4;
    const int col = j0 + threadIdx.x * 4;
    float* outp = attnW + ((size_t)z * Sq + row) * Sq + col;
    const int* mrow = mask + b * Sq + col;
    #pragma unroll
    for (int i = 0; i < 4; i++) {
        #pragma unroll
        for (int j = 0; j < 4; j++) {
            float v = acc[i][j] * 0.125f;
            if (mrow[j] == 0) v = -1e9f;
            outp[(size_t)i * Sq + j] = v;
        }
    }
}

// ---------------------------------------------------------------------------
// Kernel 3: row softmax over the last dim (1024). grid(49152), block(256)
// One read + one write per element.
// ---------------------------------------------------------------------------
__global__ __launch_bounds__(256)
void softmax_kernel(float* __restrict__ attn_out) {
    float* attnW = attn_out ? attn_out : g_attn_fallback;
    float* p = attnW + (size_t)blockIdx.x * Sq;
    const int t = threadIdx.x;

    float v[4];
    #pragma unroll
    for (int i = 0; i < 4; i++) v[i] = p[t + i * 256];

    __shared__ float red[256];
    float m = fmaxf(fmaxf(v[0], v[1]), fmaxf(v[2], v[3]));
    red[t] = m;
    __syncthreads();
    #pragma unroll
    for (int s = 128; s > 0; s >>= 1) {
        if (t < s) red[t] = fmaxf(red[t], red[t + s]);
        __syncthreads();
    }
    m = red[0];
    __syncthreads();

    float e[4], sum = 0.f;
    #pragma unroll
    for (int i = 0; i < 4; i++) { e[i] = __expf(v[i] - m); sum += e[i]; }
    red[t] = sum;
    __syncthreads();
    #pragma unroll
    for (int s = 128; s > 0; s >>= 1) {
        if (t < s) red[t] += red[t + s];
        __syncthreads();
    }
    const float inv = 1.f / red[0];
    #pragma unroll
    for (int i = 0; i < 4; i++) p[t + i * 256] = e[i] * inv;
}

// ---------------------------------------------------------------------------
// Kernel 4: ctx = attnW @ V (per head, NN). grid(1, 16, 48), block(16,16)
// Writes directly into [B,S,W] layout.
// ---------------------------------------------------------------------------
__global__ __launch_bounds__(256)
void av_kernel(const float* __restrict__ attn_in) {
    const float* attnW = attn_in ? attn_in : g_attn_fallback;
    const int z = blockIdx.z;
    const int b = z / Hh;
    const int h = z - b * Hh;
    const int i0 = blockIdx.y * BM;

    const float* A = attnW + (size_t)z * Sq * Sq + (size_t)i0 * Sq;   // [64 x 1024]
    const float* Bp = g_v + (size_t)b * Sq * Wd + h * Dd;             // [1024 x 64] (N-contig)
    float acc[4][4] = {};
    gemm_tile_body<true>(A, Sq, Bp, Wd, Sq, acc);

    const int row = i0 + threadIdx.y * 4;
    const int col = threadIdx.x * 4;
    #pragma unroll
    for (int i = 0; i < 4; i++)
        #pragma unroll
        for (int j = 0; j < 4; j++)
            g_ctx[(size_t)(b * Sq + row + i) * Wd + h * Dd + col + j] = acc[i][j];
}

// ---------------------------------------------------------------------------
// Kernel 5: output projection. grid(12, 64), block(16,16)
// ---------------------------------------------------------------------------
__global__ __launch_bounds__(256)
void oproj_kernel(const float* __restrict__ ow, const float* __restrict__ ob,
                  float* __restrict__ out) {
    const int i0 = blockIdx.y * BM;
    const int n0 = blockIdx.x * BN;
    float acc[4][4] = {};
    gemm_tile_body<false>(g_ctx + (size_t)i0 * Wd, Wd, ow + (size_t)n0 * Eq, Eq, Wd, acc);

    const int row = i0 + threadIdx.y * 4;
    const int col = n0 + threadIdx.x * 4;
    #pragma unroll
    for (int i = 0; i < 4; i++)
        #pragma unroll
        for (int j = 0; j < 4; j++)
            out[(size_t)(row + i) * Wd + col + j] = acc[i][j] + ob[col + j];
}

// ---------------------------------------------------------------------------
extern "C" void kernel_launch(void* const* d_in, const int* in_sizes, int n_in,
                              void* d_out, int out_size) {
    const float* query = (const float*)d_in[0];
    const int*   mask  = (const int*)d_in[1];
    const float* q_w = (const float*)d_in[2];
    const float* q_b = (const float*)d_in[3];
    const float* k_w = (const float*)d_in[4];
    const float* k_b = (const float*)d_in[5];
    const float* v_w = (const float*)d_in[6];
    const float* v_b = (const float*)d_in[7];
    const float* o_w = (const float*)d_in[8];
    const float* o_b = (const float*)d_in[9];

    float* out = (float*)d_out;
    // Tuple order: (output, attn_weights). If d_out holds both, attn weights go after output.
    float* attn = ((long long)out_size >= OUT_ELEMS + ATTN_ELEMS) ? out + OUT_ELEMS : nullptr;

    dim3 blk(16, 16);

    qkv_kernel<<<dim3(Wd / BN, BSq / BM, 3), blk>>>(query, q_w, q_b, k_w, k_b, v_w, v_b);
    score_kernel<<<dim3(Sq / BN, Sq / BM, Bq * Hh), blk>>>(mask, attn);
    softmax_kernel<<<dim3(Bq * Hh * Sq), dim3(256)>>>(attn);
    av_kernel<<<dim3(1, Sq / BM, Bq * Hh), blk>>>(attn);
    oproj_kernel<<<dim3(Wd / BN, BSq / BM), blk>>>(o_w, o_b, out);
}

// round 2
// speedup vs baseline: 1.2825x; 1.2825x over previous
#include <cuda_runtime.h>
#include <cstdint>

// Fixed shapes: B=4, S=1024, E=1024, width=768 -> H=12, D=64
#define Bq   4
#define Sq   1024
#define Eq   1024
#define Wd   768
#define Hh   12
#define Dd   64
#define BSq  (Bq*Sq)            // 4096
#define NZ   (Bq*Hh)            // 48
#define OUT_ELEMS   ((long long)BSq*Wd)        // 3,145,728
#define ATTN_ELEMS  ((long long)NZ*Sq*Sq)      // 50,331,648

// ---------------- scratch (device globals; no runtime allocation) ----------
__device__ __align__(16) float g_q[BSq*Wd];
__device__ __align__(16) float g_k[BSq*Wd];
__device__ __align__(16) float g_v[BSq*Wd];
__device__ __align__(16) float g_ctx[BSq*Wd];
__device__ __align__(16) float g_pm[NZ*8*Sq];    // per (z, colblock, row) partial max
__device__ __align__(16) float g_ps[NZ*8*Sq];    // per (z, colblock, row) partial sumexp
__device__ __align__(16) float g_rm[NZ*Sq];      // per-row global max
__device__ __align__(16) float g_ri[NZ*Sq];      // per-row 1/sum
__device__ __align__(16) float g_attn_fallback[NZ*Sq*Sq];

// ---------------- packed f32x2 helpers -------------------------------------
__device__ __forceinline__ unsigned long long pack2(float x, float y) {
    unsigned long long r;
    asm("mov.b64 %0, {%1, %2};" : "=l"(r) : "f"(x), "f"(y));
    return r;
}
__device__ __forceinline__ void unpack2(unsigned long long v, float& x, float& y) {
    asm("mov.b64 {%0, %1}, %2;" : "=f"(x), "=f"(y) : "l"(v));
}
__device__ __forceinline__ unsigned long long ffma2(unsigned long long a,
                                                    unsigned long long b,
                                                    unsigned long long c) {
    unsigned long long d;
    asm("fma.rn.f32x2 %0, %1, %2, %3;" : "=l"(d) : "l"(a), "l"(b), "l"(c));
    return d;
}

// ---------------------------------------------------------------------------
// 128x128 NT GEMM body: C[128,128] += A[128,K] * B[128,K]^T, both K-contiguous.
// 256 threads, 8x8 micro-tile per thread, packed-pair accumulators along N.
// ---------------------------------------------------------------------------
__device__ __forceinline__ void gemm_nt_128(const float* __restrict__ A, int lda,
                                            const float* __restrict__ B, int ldb,
                                            int K, unsigned long long (&acc)[8][4],
                                            float (&As)[16][132], float (&Bs)[16][132]) {
    const int t  = threadIdx.x;
    const int tr = t >> 4;          // 0..15 -> row0 = tr*8
    const int tc = t & 15;          // 0..15 -> col0 = tc*8
    const int lr = t >> 2;          // 0..63
    const int lk = (t & 3) << 2;    // 0,4,8,12

    for (int k0 = 0; k0 < K; k0 += 16) {
        float4 a0 = *(const float4*)(A + (size_t)lr * lda + k0 + lk);
        float4 a1 = *(const float4*)(A + (size_t)(lr + 64) * lda + k0 + lk);
        float4 b0 = *(const float4*)(B + (size_t)lr * ldb + k0 + lk);
        float4 b1 = *(const float4*)(B + (size_t)(lr + 64) * ldb + k0 + lk);
        As[lk+0][lr] = a0.x; As[lk+1][lr] = a0.y; As[lk+2][lr] = a0.z; As[lk+3][lr] = a0.w;
        As[lk+0][lr+64] = a1.x; As[lk+1][lr+64] = a1.y; As[lk+2][lr+64] = a1.z; As[lk+3][lr+64] = a1.w;
        Bs[lk+0][lr] = b0.x; Bs[lk+1][lr] = b0.y; Bs[lk+2][lr] = b0.z; Bs[lk+3][lr] = b0.w;
        Bs[lk+0][lr+64] = b1.x; Bs[lk+1][lr+64] = b1.y; Bs[lk+2][lr+64] = b1.z; Bs[lk+3][lr+64] = b1.w;
        __syncthreads();

        #pragma unroll
        for (int kk = 0; kk < 16; kk++) {
            float4 x0 = *(const float4*)&As[kk][tr * 8];
            float4 x1 = *(const float4*)&As[kk][tr * 8 + 4];
            float4 y0 = *(const float4*)&Bs[kk][tc * 8];
            float4 y1 = *(const float4*)&Bs[kk][tc * 8 + 4];
            unsigned long long bp[4] = { pack2(y0.x, y0.y), pack2(y0.z, y0.w),
                                         pack2(y1.x, y1.y), pack2(y1.z, y1.w) };
            float av[8] = { x0.x, x0.y, x0.z, x0.w, x1.x, x1.y, x1.z, x1.w };
            #pragma unroll
            for (int i = 0; i < 8; i++) {
                unsigned long long ap = pack2(av[i], av[i]);
                #pragma unroll
                for (int j = 0; j < 4; j++)
                    acc[i][j] = ffma2(ap, bp[j], acc[i][j]);
            }
        }
        __syncthreads();
    }
}

// ---------------------------------------------------------------------------
// Kernel 1: fused QKV projections. grid(6, 32, 3), block(256)
// ---------------------------------------------------------------------------
__global__ __launch_bounds__(256)
void qkv_kernel(const float* __restrict__ x,
                const float* __restrict__ qw, const float* __restrict__ qb,
                const float* __restrict__ kw, const float* __restrict__ kb,
                const float* __restrict__ vw, const float* __restrict__ vb) {
    __shared__ float As[16][132], Bs[16][132];
    const float* W; const float* bias; float* out;
    if (blockIdx.z == 0)      { W = qw; bias = qb; out = g_q; }
    else if (blockIdx.z == 1) { W = kw; bias = kb; out = g_k; }
    else                      { W = vw; bias = vb; out = g_v; }

    const int i0 = blockIdx.y * 128;
    const int n0 = blockIdx.x * 128;
    unsigned long long acc[8][4];
    #pragma unroll
    for (int i = 0; i < 8; i++)
        #pragma unroll
        for (int j = 0; j < 4; j++) acc[i][j] = 0ull;

    gemm_nt_128(x + (size_t)i0 * Eq, Eq, W + (size_t)n0 * Eq, Eq, Wd, acc, As, Bs);

    const int row0 = (threadIdx.x >> 4) * 8;
    const int col0 = (threadIdx.x & 15) * 8;
    #pragma unroll
    for (int i = 0; i < 8; i++) {
        float c[8];
        #pragma unroll
        for (int j = 0; j < 4; j++) unpack2(acc[i][j], c[2*j], c[2*j+1]);
        float* op = out + (size_t)(i0 + row0 + i) * Wd + n0 + col0;
        #pragma unroll
        for (int j = 0; j < 8; j++) op[j] = c[j] + bias[n0 + col0 + j];
    }
}

// ---------------------------------------------------------------------------
// Kernel 2: masked scores = QK^T/8 with fused per-colblock softmax partials.
// grid(8, 8, 48), block(256). Writes RAW masked scores into attn buffer and
// (max, sumexp) partials per (row, 128-col block).
// ---------------------------------------------------------------------------
__global__ __launch_bounds__(256)
void score_kernel(const int* __restrict__ mask, float* __restrict__ attn_out) {
    __shared__ float As[16][132], Bs[16][132];
    __shared__ int smask[128];
    float* attnW = attn_out ? attn_out : g_attn_fallback;

    const int z = blockIdx.z;
    const int b = z / Hh;
    const int h = z - b * Hh;
    const int i0 = blockIdx.y * 128;
    const int j0 = blockIdx.x * 128;
    const int cb = blockIdx.x;

    if (threadIdx.x < 128) smask[threadIdx.x] = mask[b * Sq + j0 + threadIdx.x];

    const float* Qp = g_q + ((size_t)b * Sq + i0) * Wd + h * Dd;
    const float* Kp = g_k + ((size_t)b * Sq + j0) * Wd + h * Dd;

    unsigned long long acc[8][4];
    #pragma unroll
    for (int i = 0; i < 8; i++)
        #pragma unroll
        for (int j = 0; j < 4; j++) acc[i][j] = 0ull;

    gemm_nt_128(Qp, Wd, Kp, Wd, Dd, acc, As, Bs);

    const int tr = threadIdx.x >> 4, tc = threadIdx.x & 15;
    const int row0 = tr * 8, col0 = tc * 8;

    #pragma unroll
    for (int i = 0; i < 8; i++) {
        const int r = i0 + row0 + i;
        float v[8];
        #pragma unroll
        for (int j = 0; j < 4; j++) unpack2(acc[i][j], v[2*j], v[2*j+1]);
        #pragma unroll
        for (int j = 0; j < 8; j++) {
            float x = v[j] * 0.125f;
            if (smask[col0 + j] == 0) x = -1e9f;
            v[j] = x;
        }
        // write raw masked scores
        float* op = attnW + ((size_t)z * Sq + r) * Sq + j0 + col0;
        *(float4*)&op[0] = make_float4(v[0], v[1], v[2], v[3]);
        *(float4*)&op[4] = make_float4(v[4], v[5], v[6], v[7]);

        // per-row partial softmax stats across this 128-col block
        float m = v[0];
        #pragma unroll
        for (int j = 1; j < 8; j++) m = fmaxf(m, v[j]);
        #pragma unroll
        for (int o = 1; o < 16; o <<= 1)
            m = fmaxf(m, __shfl_xor_sync(0xffffffffu, m, o));
        float s = 0.f;
        #pragma unroll
        for (int j = 0; j < 8; j++) s += __expf(v[j] - m);
        #pragma unroll
        for (int o = 1; o < 16; o <<= 1)
            s += __shfl_xor_sync(0xffffffffu, s, o);
        if (tc == 0) {
            g_pm[((size_t)z * 8 + cb) * Sq + r] = m;
            g_ps[((size_t)z * 8 + cb) * Sq + r] = s;
        }
    }
}

// ---------------------------------------------------------------------------
// Kernel 3: combine 8 partials per row -> (row max, 1/row sum). grid(192),256.
// ---------------------------------------------------------------------------
__global__ __launch_bounds__(256)
void combine_kernel() {
    const int idx = blockIdx.x * 256 + threadIdx.x;   // z*1024 + r
    const int z = idx >> 10, r = idx & 1023;
    float m = -3.4e38f;
    float pm[8], ps[8];
    #pragma unroll
    for (int cb = 0; cb < 8; cb++) {
        pm[cb] = g_pm[((size_t)z * 8 + cb) * Sq + r];
        ps[cb] = g_ps[((size_t)z * 8 + cb) * Sq + r];
        m = fmaxf(m, pm[cb]);
    }
    float s = 0.f;
    #pragma unroll
    for (int cb = 0; cb < 8; cb++) s += ps[cb] * __expf(pm[cb] - m);
    g_rm[idx] = m;
    g_ri[idx] = 1.0f / s;
}

// ---------------------------------------------------------------------------
// Kernel 4: normalize + AV. grid(8, 48), block(256).
// Reads raw scores, computes p = exp(v-m)/S, writes p back in place (this is
// the attn_weights output), and accumulates ctx = P @ V with 128x64 tiles.
// ---------------------------------------------------------------------------
__global__ __launch_bounds__(256)
void av_kernel(float* __restrict__ attn_out) {
    __shared__ float As[16][132], Bs[16][72];
    __shared__ float sm[128], si[128];
    float* attnW = attn_out ? attn_out : g_attn_fallback;

    const int z = blockIdx.y;
    const int b = z / Hh;
    const int h = z - b * Hh;
    const int i0 = blockIdx.x * 128;
    const int t = threadIdx.x;

    if (t < 128) {
        sm[t] = g_rm[z * Sq + i0 + t];
        si[t] = g_ri[z * Sq + i0 + t];
    }
    __syncthreads();

    float* Arow = attnW + ((size_t)z * Sq + i0) * Sq;        // [128][1024]
    const float* Vp = g_v + (size_t)b * Sq * Wd + h * Dd;    // [1024][64] stride 768

    const int tr = t >> 4, tc = t & 15;
    const int row0 = tr * 8, col0 = tc * 4;
    const int lr = t >> 2, lk = (t & 3) << 2;
    const int vk = t >> 4, vn = (t & 15) << 2;

    unsigned long long acc[8][2];
    #pragma unroll
    for (int i = 0; i < 8; i++) { acc[i][0] = 0ull; acc[i][1] = 0ull; }

    for (int k0 = 0; k0 < Sq; k0 += 16) {
        // load raw scores, normalize, stage to smem, write back normalized
        #pragma unroll
        for (int half = 0; half < 2; half++) {
            const int r = lr + half * 64;
            float* ap = Arow + (size_t)r * Sq + k0 + lk;
            float4 v4 = *(const float4*)ap;
            const float mr = sm[r], ir = si[r];
            float4 p;
            p.x = __expf(v4.x - mr) * ir;
            p.y = __expf(v4.y - mr) * ir;
            p.z = __expf(v4.z - mr) * ir;
            p.w = __expf(v4.w - mr) * ir;
            As[lk+0][r] = p.x; As[lk+1][r] = p.y; As[lk+2][r] = p.z; As[lk+3][r] = p.w;
            *(float4*)ap = p;
        }
        // load V tile
        float4 w4 = *(const float4*)(Vp + (size_t)(k0 + vk) * Wd + vn);
        *(float4*)&Bs[vk][vn] = w4;
        __syncthreads();

        #pragma unroll
        for (int kk = 0; kk < 16; kk++) {
            float4 x0 = *(const float4*)&As[kk][row0];
            float4 x1 = *(const float4*)&As[kk][row0 + 4];
            float4 y  = *(const float4*)&Bs[kk][col0];
            unsigned long long bp0 = pack2(y.x, y.y);
            unsigned long long bp1 = pack2(y.z, y.w);
            float av[8] = { x0.x, x0.y, x0.z, x0.w, x1.x, x1.y, x1.z, x1.w };
            #pragma unroll
            for (int i = 0; i < 8; i++) {
                unsigned long long ap = pack2(av[i], av[i]);
                acc[i][0] = ffma2(ap, bp0, acc[i][0]);
                acc[i][1] = ffma2(ap, bp1, acc[i][1]);
            }
        }
        __syncthreads();
    }

    #pragma unroll
    for (int i = 0; i < 8; i++) {
        float c0, c1, c2, c3;
        unpack2(acc[i][0], c0, c1);
        unpack2(acc[i][1], c2, c3);
        float* op = g_ctx + ((size_t)b * Sq + i0 + row0 + i) * Wd + h * Dd + col0;
        *(float4*)op = make_float4(c0, c1, c2, c3);
    }
}

// ---------------------------------------------------------------------------
// Kernel 5: output projection. grid(6, 32), block(256).
// ---------------------------------------------------------------------------
__global__ __launch_bounds__(256)
void oproj_kernel(const float* __restrict__ ow, const float* __restrict__ ob,
                  float* __restrict__ out) {
    __shared__ float As[16][132], Bs[16][132];
    const int i0 = blockIdx.y * 128;
    const int n0 = blockIdx.x * 128;
    unsigned long long acc[8][4];
    #pragma unroll
    for (int i = 0; i < 8; i++)
        #pragma unroll
        for (int j = 0; j < 4; j++) acc[i][j] = 0ull;

    gemm_nt_128(g_ctx + (size_t)i0 * Wd, Wd, ow + (size_t)n0 * Eq, Eq, Wd, acc, As, Bs);

    const int row0 = (threadIdx.x >> 4) * 8;
    const int col0 = (threadIdx.x & 15) * 8;
    #pragma unroll
    for (int i = 0; i < 8; i++) {
        float c[8];
        #pragma unroll
        for (int j = 0; j < 4; j++) unpack2(acc[i][j], c[2*j], c[2*j+1]);
        float* op = out + (size_t)(i0 + row0 + i) * Wd + n0 + col0;
        #pragma unroll
        for (int j = 0; j < 8; j++) op[j] = c[j] + ob[n0 + col0 + j];
    }
}

// ---------------------------------------------------------------------------
extern "C" void kernel_launch(void* const* d_in, const int* in_sizes, int n_in,
                              void* d_out, int out_size) {
    const float* query = (const float*)d_in[0];
    const int*   mask  = (const int*)d_in[1];
    const float* q_w = (const float*)d_in[2];
    const float* q_b = (const float*)d_in[3];
    const float* k_w = (const float*)d_in[4];
    const float* k_b = (const float*)d_in[5];
    const float* v_w = (const float*)d_in[6];
    const float* v_b = (const float*)d_in[7];
    const float* o_w = (const float*)d_in[8];
    const float* o_b = (const float*)d_in[9];

    float* out = (float*)d_out;
    float* attn = ((long long)out_size >= OUT_ELEMS + ATTN_ELEMS) ? out + OUT_ELEMS : nullptr;

    qkv_kernel<<<dim3(Wd / 128, BSq / 128, 3), 256>>>(query, q_w, q_b, k_w, k_b, v_w, v_b);
    score_kernel<<<dim3(8, 8, NZ), 256>>>(mask, attn);
    combine_kernel<<<dim3(NZ * Sq / 256), 256>>>();
    av_kernel<<<dim3(8, NZ), 256>>>(attn);
    oproj_kernel<<<dim3(Wd / 128, BSq / 128), 256>>>(o_w, o_b, out);
}